// round 6
// baseline (speedup 1.0000x reference)
#include <cuda_runtime.h>
#include <math.h>
#include <stdint.h>

#define B_  256
#define T_  512
#define D_  128
#define H_  256
#define G_  768
#define C_  10

#define NCTA_SCAN 128
#define GRP_CTAS  32

typedef unsigned long long ull;

// packed fp32x2 FMA for the batched GEMM (throughput-neutral, issue-friendly)
#define FMA2(d, a, b) \
    asm("fma.rn.f32x2 %0, %1, %2, %0;" : "+l"(d) : "l"(a), "l"(b))
#define DUP2(d, f) \
    asm("mov.b64 %0, {%1, %1};" : "=l"(d) : "f"(f))

// ---------------- scratch (device globals; no allocation allowed) ----------------
__device__ float g_gi[(size_t)B_ * T_ * G_];   // gi for current layer (~403 MB)
__device__ float g_h1[(size_t)T_ * B_ * H_];   // layer-0 hidden states, [T][B][H]
__device__ float g_hbuf[2][B_ * H_];           // ping-pong h, layout [jblk 32][B 256][8]
__device__ volatile unsigned g_flag[4][32 * 32]; // per-group arrival flags (128B slots)

// ---------------- SGEMM: C[M,768] = A[M,K] @ W[768,K]^T + bias -------------------
__global__ void __launch_bounds__(256, 2) gemm_nt(
    const float* __restrict__ A, const float* __restrict__ W,
    const float* __restrict__ bias, float* __restrict__ C, int K)
{
    __shared__ float As[16][128];
    __shared__ float Ws[16][128];

    const int m0 = blockIdx.x * 128;
    const int n0 = blockIdx.y * 128;
    const int tid = threadIdx.x;
    const int tx = tid & 15;
    const int ty = tid >> 4;

    const int f0 = tid * 2, f1 = tid * 2 + 1;
    const int am0 = f0 >> 2, ak0 = (f0 & 3) * 4;
    const int am1 = f1 >> 2, ak1 = (f1 & 3) * 4;

    const float* Ap = A + (size_t)m0 * K;
    const float* Wp = W + (size_t)n0 * K;

    float4 pa0 = *(const float4*)(Ap + (size_t)am0 * K + ak0);
    float4 pa1 = *(const float4*)(Ap + (size_t)am1 * K + ak1);
    float4 pw0 = *(const float4*)(Wp + (size_t)am0 * K + ak0);
    float4 pw1 = *(const float4*)(Wp + (size_t)am1 * K + ak1);

    ull acc2[8][4];
#pragma unroll
    for (int i = 0; i < 8; i++)
#pragma unroll
        for (int jp = 0; jp < 4; jp++) acc2[i][jp] = 0ull;

    const int nkt = K >> 4;
    for (int kb = 0; kb < nkt; kb++) {
        As[ak0 + 0][am0] = pa0.x; As[ak0 + 1][am0] = pa0.y;
        As[ak0 + 2][am0] = pa0.z; As[ak0 + 3][am0] = pa0.w;
        As[ak1 + 0][am1] = pa1.x; As[ak1 + 1][am1] = pa1.y;
        As[ak1 + 2][am1] = pa1.z; As[ak1 + 3][am1] = pa1.w;
        Ws[ak0 + 0][am0] = pw0.x; Ws[ak0 + 1][am0] = pw0.y;
        Ws[ak0 + 2][am0] = pw0.z; Ws[ak0 + 3][am0] = pw0.w;
        Ws[ak1 + 0][am1] = pw1.x; Ws[ak1 + 1][am1] = pw1.y;
        Ws[ak1 + 2][am1] = pw1.z; Ws[ak1 + 3][am1] = pw1.w;
        __syncthreads();

        if (kb + 1 < nkt) {
            const int ko = (kb + 1) * 16;
            pa0 = *(const float4*)(Ap + (size_t)am0 * K + ko + ak0);
            pa1 = *(const float4*)(Ap + (size_t)am1 * K + ko + ak1);
            pw0 = *(const float4*)(Wp + (size_t)am0 * K + ko + ak0);
            pw1 = *(const float4*)(Wp + (size_t)am1 * K + ko + ak1);
        }

#pragma unroll
        for (int k = 0; k < 16; k++) {
            float av[8];
            *(float4*)&av[0] = *(const float4*)&As[k][ty * 4];
            *(float4*)&av[4] = *(const float4*)&As[k][64 + ty * 4];
            ull wv2[4];
            {
                const ulonglong2 w0 = *(const ulonglong2*)&Ws[k][tx * 4];
                const ulonglong2 w1 = *(const ulonglong2*)&Ws[k][64 + tx * 4];
                wv2[0] = w0.x; wv2[1] = w0.y; wv2[2] = w1.x; wv2[3] = w1.y;
            }
#pragma unroll
            for (int i = 0; i < 8; i++) {
                ull ad; DUP2(ad, av[i]);
#pragma unroll
                for (int jp = 0; jp < 4; jp++) FMA2(acc2[i][jp], ad, wv2[jp]);
            }
        }
        __syncthreads();
    }

#pragma unroll
    for (int i = 0; i < 8; i++) {
        const int mrow = m0 + ty * 4 + (i & 3) + ((i >> 2) * 64);
        const int c0 = n0 + tx * 4;
        const float2 a0 = *(float2*)&acc2[i][0];
        const float2 a1 = *(float2*)&acc2[i][1];
        const float2 a2 = *(float2*)&acc2[i][2];
        const float2 a3 = *(float2*)&acc2[i][3];
        float4 o0, o1;
        o0.x = a0.x + bias[c0 + 0];
        o0.y = a0.y + bias[c0 + 1];
        o0.z = a1.x + bias[c0 + 2];
        o0.w = a1.y + bias[c0 + 3];
        o1.x = a2.x + bias[c0 + 64 + 0];
        o1.y = a2.y + bias[c0 + 64 + 1];
        o1.z = a3.x + bias[c0 + 64 + 2];
        o1.w = a3.y + bias[c0 + 64 + 3];
        *(float4*)&C[(size_t)mrow * G_ + c0]       = o0;
        *(float4*)&C[(size_t)mrow * G_ + c0 + 64]  = o1;
    }
}

// ---------------- reset barrier flags (graph-replay safe) -------------------------
__global__ void reset_flags()
{
    int i = blockIdx.x * blockDim.x + threadIdx.x;
    if (i < 4 * 32 * 32) ((unsigned*)g_flag)[i] = 0u;
}

// ---------------- persistent GRU scan, v4: 16 warps, flag barrier -----------------
// 128 CTAs x 512 threads. CTA (bblk 0..3, jblk 0..31): 64 batches x 8 hidden dims.
// 16-way split-K (16 k per warp), 8b x 6g lane tiles, part[16][64][25],
// h ping-pong in [jblk][B][8] layout (coalesced 2KB writeback per CTA).
__global__ void __launch_bounds__(512, 1) gru_scan(
    const float* __restrict__ gi, const float* __restrict__ Whh,
    const float* __restrict__ bhh, float* __restrict__ hseq, int tmajor)
{
    extern __shared__ float sm[];
    float* wsl  = sm;                 // [24][260]    = 6240
    float* bsl  = sm + 6240;          // [24] pad 32
    float* hs   = sm + 6272;          // [64][260]    = 16640
    float* part = sm + 22912;         // [16][64][25] = 25600
    float* gis  = sm + 48512;         // [64*25]      = 1600
    float* hst  = sm + 50112;         // [64][9]      = 576   (total 50688 floats)

    const int tid = threadIdx.x;
    const int cta = blockIdx.x;
    const int bblk = cta >> 5;
    const int jblk = cta & 31;
    const int b0  = bblk * 64;
    const int j0  = jblk * 8;

    // persistent Whh slice: rows {j0..j0+7, H+j0.., 2H+j0..}
    for (int idx = tid; idx < 24 * 256; idx += 512) {
        const int row = idx >> 8, k = idx & 255;
        wsl[row * 260 + k] = Whh[(size_t)((row >> 3) * H_ + j0 + (row & 7)) * H_ + k];
    }
    if (tid < 24) bsl[tid] = bhh[(tid >> 3) * H_ + j0 + (tid & 7)];

    const int w     = tid >> 5, lane = tid & 31;
    const int kbase = w * 16;
    const int bl    = lane & 7;
    const int g0l   = (lane >> 3) * 6;

    // per-thread gi staging map (3 elements), fixed across steps
    int gq_b[3], gq_sm[3], gq_col[3];
#pragma unroll
    for (int q = 0; q < 3; q++) {
        const int idx = tid + 512 * q;
        const int b = idx / 24, gg = idx % 24;
        gq_b[q] = b;
        gq_sm[q] = b * 25 + gg;
        gq_col[q] = (gg >> 3) * H_ + j0 + (gg & 7);
    }

    // stage gi(t=0)
    float greg[3];
#pragma unroll
    for (int q = 0; q < 3; q++) {
        const size_t row = tmajor ? ((size_t)0 * B_ + b0 + gq_b[q])
                                  : ((size_t)(b0 + gq_b[q]) * T_ + 0);
        greg[q] = gi[row * G_ + gq_col[q]];
    }
#pragma unroll
    for (int q = 0; q < 3; q++) gis[gq_sm[q]] = greg[q];
    __syncthreads();

    for (int t = 0; t < T_; t++) {
        const float* hprev = g_hbuf[t & 1];
        float* hnext = g_hbuf[(t & 1) ^ 1];

        // ---- stage h_prev [jblk][B][8] -> hs[64][260] (float4, coalesced) ----
        if (t == 0) {
            const float4 z4 = make_float4(0.f, 0.f, 0.f, 0.f);
#pragma unroll
            for (int q = 0; q < 8; q++) {
                const int v = tid + 512 * q;
                const int jb = v >> 7, b = (v >> 1) & 63, jq = v & 1;
                *(float4*)&hs[b * 260 + jb * 8 + jq * 4] = z4;
            }
        } else {
#pragma unroll
            for (int q = 0; q < 8; q++) {
                const int v = tid + 512 * q;
                const int jb = v >> 7, b = (v >> 1) & 63, jq = v & 1;
                *(float4*)&hs[b * 260 + jb * 8 + jq * 4] =
                    *(const float4*)&hprev[jb * 2048 + (b0 + b) * 8 + jq * 4];
            }
        }

        // ---- prefetch gi(t+1) into registers (hidden under GEMM) ----
        {
            const int tn = (t + 1 < T_) ? (t + 1) : t;
#pragma unroll
            for (int q = 0; q < 3; q++) {
                const size_t row = tmajor ? ((size_t)tn * B_ + b0 + gq_b[q])
                                          : ((size_t)(b0 + gq_b[q]) * T_ + tn);
                greg[q] = __ldg(&gi[row * G_ + gq_col[q]]);
            }
        }
        __syncthreads();

        // ---- 16-way split-K partial GEMM: gh_partial[64][24], k in [kbase, kbase+16) ----
        float acc[8][6];
#pragma unroll
        for (int i = 0; i < 8; i++)
#pragma unroll
            for (int g = 0; g < 6; g++) acc[i][g] = 0.f;

#pragma unroll
        for (int kb = 0; kb < 4; kb++) {
            const int k = kbase + kb * 4;
            float4 wv[6];
#pragma unroll
            for (int g = 0; g < 6; g++)
                wv[g] = *(const float4*)&wsl[(g0l + g) * 260 + k];
#pragma unroll
            for (int i = 0; i < 8; i++) {
                const float4 hv = *(const float4*)&hs[(bl + 8 * i) * 260 + k];
#pragma unroll
                for (int g = 0; g < 6; g++) {
                    acc[i][g] += hv.x * wv[g].x;
                    acc[i][g] += hv.y * wv[g].y;
                    acc[i][g] += hv.z * wv[g].z;
                    acc[i][g] += hv.w * wv[g].w;
                }
            }
        }
#pragma unroll
        for (int i = 0; i < 8; i++) {
            float* p = &part[(w * 64 + bl + 8 * i) * 25 + g0l];
#pragma unroll
            for (int g = 0; g < 6; g++) p[g] = acc[i][g];
        }
        __syncthreads();

        // ---- reduce 16 partials + gate math (one (b,jj) per thread) ----
        {
            const int b = tid & 63, jj = tid >> 6;
            float sr = bsl[jj], sz = bsl[8 + jj], sn = bsl[16 + jj];
#pragma unroll
            for (int ww = 0; ww < 16; ww++) {
                const float* pp = &part[(ww * 64 + b) * 25];
                sr += pp[jj];
                sz += pp[8 + jj];
                sn += pp[16 + jj];
            }
            sr += gis[b * 25 + jj];
            sz += gis[b * 25 + 8 + jj];
            const float r = __fdividef(1.f, 1.f + __expf(-sr));
            const float z = __fdividef(1.f, 1.f + __expf(-sz));
            const float a = gis[b * 25 + 16 + jj] + r * sn;
            const float n = __fdividef(2.f, 1.f + __expf(-2.f * a)) - 1.f;
            const float hold = hs[b * 260 + j0 + jj];
            hst[b * 9 + jj] = (1.f - z) * n + z * hold;
        }
        __syncthreads();

        // ---- writeback h_new (contiguous 2KB burst), hseq, stash gi(t+1) ----
        if (tid < 128) {
            const int b = tid >> 1, jj4 = (tid & 1) * 4;
            float4 o;
            o.x = hst[b * 9 + jj4 + 0];
            o.y = hst[b * 9 + jj4 + 1];
            o.z = hst[b * 9 + jj4 + 2];
            o.w = hst[b * 9 + jj4 + 3];
            *(float4*)&hnext[jblk * 2048 + b0 * 8 + tid * 4] = o;
        }
        if (hseq) {
            const int b = tid >> 3, jj = tid & 7;
            hseq[((size_t)t * B_ + b0 + b) * H_ + j0 + jj] = hst[b * 9 + jj];
        }
#pragma unroll
        for (int q = 0; q < 3; q++) gis[gq_sm[q]] = greg[q];

        // ---- per-group (32 CTA) flag barrier ----
        __threadfence();
        __syncthreads();
        if (tid == 0) g_flag[bblk][jblk * 32] = (unsigned)(t + 1);
        if (tid < 32) {
            while (__any_sync(0xffffffffu, g_flag[bblk][tid * 32] < (unsigned)(t + 1))) {}
        }
        if (tid == 0) __threadfence();   // CCTL.IVALL: flush L1 before reading peers' h
        __syncthreads();
    }
}

// ---------------- final FC: out[256,10] = h @ Wfc^T + bfc -------------------------
// h in [jblk][B][8] layout
__global__ void fc_kernel(const float* __restrict__ h, const float* __restrict__ Wfc,
                          const float* __restrict__ bfc, float* __restrict__ out)
{
    const int b = blockIdx.x;
    const int lane = threadIdx.x;
    float hv[8];
#pragma unroll
    for (int i = 0; i < 8; i++) {
        const int k = lane + 32 * i;
        hv[i] = h[(k >> 3) * 2048 + b * 8 + (k & 7)];
    }
    for (int cc = 0; cc < C_; cc++) {
        float s = 0.f;
#pragma unroll
        for (int i = 0; i < 8; i++) s += hv[i] * Wfc[cc * H_ + lane + 32 * i];
#pragma unroll
        for (int o = 16; o > 0; o >>= 1) s += __shfl_down_sync(0xffffffffu, s, o);
        if (lane == 0) out[b * C_ + cc] = s + bfc[cc];
    }
}

// ---------------- launch ----------------------------------------------------------
extern "C" void kernel_launch(void* const* d_in, const int* in_sizes, int n_in,
                              void* d_out, int out_size)
{
    (void)in_sizes; (void)n_in; (void)out_size;
    const float* x    = (const float*)d_in[0];
    const float* Wih0 = (const float*)d_in[1];
    const float* Whh0 = (const float*)d_in[2];
    const float* bih0 = (const float*)d_in[3];
    const float* bhh0 = (const float*)d_in[4];
    const float* Wih1 = (const float*)d_in[5];
    const float* Whh1 = (const float*)d_in[6];
    const float* bih1 = (const float*)d_in[7];
    const float* bhh1 = (const float*)d_in[8];
    const float* Wfc  = (const float*)d_in[9];
    const float* bfc  = (const float*)d_in[10];
    float* out = (float*)d_out;

    float *p_gi, *p_h1, *p_hb;
    cudaGetSymbolAddress((void**)&p_gi, g_gi);
    cudaGetSymbolAddress((void**)&p_h1, g_h1);
    cudaGetSymbolAddress((void**)&p_hb, g_hbuf);

    const int scan_smem = 50688 * 4;
    cudaFuncSetAttribute(gru_scan, cudaFuncAttributeMaxDynamicSharedMemorySize, scan_smem);

    const dim3 gg(1024, 6);

    // layer 0: gi0 = x @ Wih0^T + bih0   (gi layout [B][T][768])
    gemm_nt<<<gg, 256>>>(x, Wih0, bih0, p_gi, D_);
    reset_flags<<<16, 256>>>();
    gru_scan<<<NCTA_SCAN, 512, scan_smem>>>(p_gi, Whh0, bhh0, p_h1, /*tmajor=*/0);

    // layer 1: gi1 = h1 @ Wih1^T + bih1  (h1 and gi1 in [T][B][*] layout)
    gemm_nt<<<gg, 256>>>(p_h1, Wih1, bih1, p_gi, H_);
    reset_flags<<<16, 256>>>();
    gru_scan<<<NCTA_SCAN, 512, scan_smem>>>(p_gi, Whh1, bhh1, nullptr, /*tmajor=*/1);

    // classifier on final hidden state (in g_hbuf[0] after 512 steps)
    fc_kernel<<<B_, 32>>>(p_hb, Wfc, bfc, out);
}

// round 8
// speedup vs baseline: 1.1305x; 1.1305x over previous
#include <cuda_runtime.h>
#include <cuda_bf16.h>
#include <math.h>
#include <stdint.h>

#define B_  256
#define T_  512
#define D_  128
#define H_  256
#define G_  768
#define C_  10

#define NCTA_SCAN 128
#define GRP_CTAS  32

// ---------------- warp-mma helpers (sm_80+ baseline; compiles for plain sm_103) ---
__device__ __forceinline__ uint32_t smem_u32(const void* p) {
    uint32_t a;
    asm("{ .reg .u64 t; cvta.to.shared.u64 t, %1; cvt.u32.u64 %0, t; }" : "=r"(a) : "l"(p));
    return a;
}
#define LDSM4(r0, r1, r2, r3, addr) \
    asm volatile("ldmatrix.sync.aligned.m8n8.x4.shared.b16 {%0,%1,%2,%3}, [%4];" \
        : "=r"(r0), "=r"(r1), "=r"(r2), "=r"(r3) : "r"(addr))
#define MMA16816(c, a, b) \
    asm volatile("mma.sync.aligned.m16n8k16.row.col.f32.bf16.bf16.f32 " \
        "{%0,%1,%2,%3},{%4,%5,%6,%7},{%8,%9},{%0,%1,%2,%3};" \
        : "+f"((c)[0]), "+f"((c)[1]), "+f"((c)[2]), "+f"((c)[3]) \
        : "r"((a)[0]), "r"((a)[1]), "r"((a)[2]), "r"((a)[3]), "r"((b)[0]), "r"((b)[1]))

// ---------------- scratch (device globals; no allocation allowed) ----------------
__device__ float g_gi[(size_t)B_ * T_ * G_];   // gi for current layer (~403 MB)
__device__ float g_h1[(size_t)T_ * B_ * H_];   // layer-0 hidden states, [T][B][H]
__device__ float g_hbuf[2][B_ * H_];           // ping-pong hidden state [B][H]
__device__ volatile unsigned g_gen[4 * 32];    // per-group barrier generation (padded)
__device__ unsigned g_cnt[4 * 32];             // per-group arrival counter
__device__ __nv_bfloat16 g_ahi[(size_t)131072 * 256];
__device__ __nv_bfloat16 g_alo[(size_t)131072 * 256];
__device__ __nv_bfloat16 g_whi[G_ * H_];
__device__ __nv_bfloat16 g_wlo[G_ * H_];

// ---------------- fp32 -> (bf16 hi, bf16 lo) split ---------------------------------
__global__ void split_bf16(const float* __restrict__ s, __nv_bfloat16* __restrict__ hi,
                           __nv_bfloat16* __restrict__ lo, int n4)
{
    const int i = blockIdx.x * blockDim.x + threadIdx.x;
    if (i >= n4) return;
    const float4 v = ((const float4*)s)[i];
    __nv_bfloat16 h0 = __float2bfloat16(v.x);
    __nv_bfloat16 h1 = __float2bfloat16(v.y);
    __nv_bfloat16 h2 = __float2bfloat16(v.z);
    __nv_bfloat16 h3 = __float2bfloat16(v.w);
    __nv_bfloat16 l0 = __float2bfloat16(v.x - __bfloat162float(h0));
    __nv_bfloat16 l1 = __float2bfloat16(v.y - __bfloat162float(h1));
    __nv_bfloat16 l2 = __float2bfloat16(v.z - __bfloat162float(h2));
    __nv_bfloat16 l3 = __float2bfloat16(v.w - __bfloat162float(h3));
    __nv_bfloat162* hp = (__nv_bfloat162*)hi;
    __nv_bfloat162* lp = (__nv_bfloat162*)lo;
    hp[i * 2 + 0] = __nv_bfloat162(h0, h1);
    hp[i * 2 + 1] = __nv_bfloat162(h2, h3);
    lp[i * 2 + 0] = __nv_bfloat162(l0, l1);
    lp[i * 2 + 1] = __nv_bfloat162(l2, l3);
}

// ---------------- split-bf16 HMMA GEMM: C[M,768] = A[M,K]@W[768,K]^T + bias -------
// CTA tile 128m x 64n, 8 warps (4m x 2n), warp tile 32x32 (2 x 4 m16n8k16 tiles).
// Full K resident in smem; +16B row pad makes ldmatrix conflict-free.
// D = Ahi*Whi + Ahi*Wlo + Alo*Whi, fp32 accumulation in registers.
__global__ void __launch_bounds__(256, 1) mma_gemm(
    const __nv_bfloat16* __restrict__ Ahi, const __nv_bfloat16* __restrict__ Alo,
    const __nv_bfloat16* __restrict__ Whi, const __nv_bfloat16* __restrict__ Wlo,
    const float* __restrict__ bias, float* __restrict__ C, int K)
{
    extern __shared__ char smem[];
    const int KS = K + 8;                 // padded row length (bf16 elems)
    const int strB = KS * 2;              // row stride in bytes
    char* sAhi = smem;
    char* sAlo = sAhi + 128 * strB;
    char* sWhi = sAlo + 128 * strB;
    char* sWlo = sWhi + 64 * strB;

    const int tid = threadIdx.x;
    const int n0 = blockIdx.x * 64;
    const int m0 = blockIdx.y * 128;

    // ---- stage operand tiles (uint4 = 8 bf16 per chunk) ----
    const int cpr = K >> 3;
    for (int c = tid; c < 128 * cpr; c += 256) {
        const int r = c / cpr, kc = c % cpr;
        const size_t src = (size_t)(m0 + r) * K + kc * 8;
        *(uint4*)(sAhi + r * strB + kc * 16) = *(const uint4*)(Ahi + src);
        *(uint4*)(sAlo + r * strB + kc * 16) = *(const uint4*)(Alo + src);
    }
    for (int c = tid; c < 64 * cpr; c += 256) {
        const int r = c / cpr, kc = c % cpr;
        const size_t src = (size_t)(n0 + r) * K + kc * 8;
        *(uint4*)(sWhi + r * strB + kc * 16) = *(const uint4*)(Whi + src);
        *(uint4*)(sWlo + r * strB + kc * 16) = *(const uint4*)(Wlo + src);
    }
    __syncthreads();

    const int wid = tid >> 5, lane = tid & 31;
    const int mw = wid >> 1, nw = wid & 1;

    float acc[2][4][4];
#pragma unroll
    for (int mt = 0; mt < 2; mt++)
#pragma unroll
        for (int nt = 0; nt < 4; nt++)
#pragma unroll
            for (int q = 0; q < 4; q++) acc[mt][nt][q] = 0.f;

    // ldmatrix lane addressing (see theory: x4 group order matches fragment order)
    const int aRow = mw * 32 + (lane & 15);
    const int aKof = (lane >> 4) * 16;                       // bytes (8 bf16)
    const int bRow = nw * 32 + (lane & 7) + ((lane >> 4) << 3);
    const int bKof = ((lane >> 3) & 1) * 16;                 // bytes

    const uint32_t uAhi = smem_u32(sAhi), uAlo = smem_u32(sAlo);
    const uint32_t uWhi = smem_u32(sWhi), uWlo = smem_u32(sWlo);

    const int nks = K >> 4;
    for (int ks = 0; ks < nks; ks++) {
        const int kb = ks * 32;                              // bytes of 16 bf16
        uint32_t ah[2][4], al[2][4], bh[4][2], bl[4][2];
#pragma unroll
        for (int mt = 0; mt < 2; mt++) {
            const uint32_t ra = (uint32_t)((aRow + mt * 16) * strB + kb + aKof);
            LDSM4(ah[mt][0], ah[mt][1], ah[mt][2], ah[mt][3], uAhi + ra);
            LDSM4(al[mt][0], al[mt][1], al[mt][2], al[mt][3], uAlo + ra);
        }
#pragma unroll
        for (int np = 0; np < 2; np++) {
            const uint32_t rb = (uint32_t)((bRow + np * 16) * strB + kb + bKof);
            uint32_t t0, t1, t2, t3;
            LDSM4(t0, t1, t2, t3, uWhi + rb);
            bh[np * 2][0] = t0; bh[np * 2][1] = t1;
            bh[np * 2 + 1][0] = t2; bh[np * 2 + 1][1] = t3;
            LDSM4(t0, t1, t2, t3, uWlo + rb);
            bl[np * 2][0] = t0; bl[np * 2][1] = t1;
            bl[np * 2 + 1][0] = t2; bl[np * 2 + 1][1] = t3;
        }
#pragma unroll
        for (int mt = 0; mt < 2; mt++)
#pragma unroll
            for (int nt = 0; nt < 4; nt++) {
                MMA16816(acc[mt][nt], ah[mt], bh[nt]);
                MMA16816(acc[mt][nt], ah[mt], bl[nt]);
                MMA16816(acc[mt][nt], al[mt], bh[nt]);
            }
    }

    // ---- epilogue: D fragment (row t/4 {+8}, col 2(t%4)+{0,1}) + bias ----
#pragma unroll
    for (int mt = 0; mt < 2; mt++)
#pragma unroll
        for (int nt = 0; nt < 4; nt++) {
            const int row = m0 + mw * 32 + mt * 16 + (lane >> 2);
            const int col = n0 + nw * 32 + nt * 8 + (lane & 3) * 2;
            const float b0 = bias[col], b1 = bias[col + 1];
            float2 o0, o1;
            o0.x = acc[mt][nt][0] + b0; o0.y = acc[mt][nt][1] + b1;
            o1.x = acc[mt][nt][2] + b0; o1.y = acc[mt][nt][3] + b1;
            *(float2*)&C[(size_t)row * G_ + col]       = o0;
            *(float2*)&C[(size_t)(row + 8) * G_ + col] = o1;
        }
}

// ---------------- persistent GRU scan (proven R4 version, verbatim) ---------------
__global__ void __launch_bounds__(256, 1) gru_scan(
    const float* __restrict__ gi, const float* __restrict__ Whh,
    const float* __restrict__ bhh, float* __restrict__ hseq, int tmajor)
{
    extern __shared__ float sm[];
    float* wsl  = sm;                 // [24][260]   = 6240
    float* bsl  = sm + 6240;          // [24] pad 32
    float* hs   = sm + 6272;          // [64][260]   = 16640
    float* part = sm + 22912;         // [8][64][25] = 12800
    float* gis  = sm + 35712;         // [2][64*25]  = 3200
    float* hst  = sm + 38912;         // [64][9]     = 576   (total 39488 floats)

    const int tid = threadIdx.x;
    const int cta = blockIdx.x;
    const int b0  = (cta >> 5) * 64;
    const int j0  = (cta & 31) * 8;
    const int grp = (cta >> 5) * 32;

    for (int idx = tid; idx < 24 * 256; idx += 256) {
        const int row = idx >> 8, k = idx & 255;
        wsl[row * 260 + k] = Whh[(size_t)((row >> 3) * H_ + j0 + (row & 7)) * H_ + k];
    }
    if (tid < 24) bsl[tid] = bhh[(tid >> 3) * H_ + j0 + (tid & 7)];

    const int w    = tid >> 5, lane = tid & 31;
    const int kbase = w * 32;
    const int bl   = lane & 7;
    const int g0l  = (lane >> 3) * 6;

    int gq_b[6], gq_sm[6], gq_col[6];
#pragma unroll
    for (int q = 0; q < 6; q++) {
        const int idx = tid + 256 * q;
        const int b = idx / 24, gg = idx % 24;
        gq_b[q] = b;
        gq_sm[q] = b * 25 + gg;
        gq_col[q] = (gg >> 3) * H_ + j0 + (gg & 7);
    }

    float greg[6];
#pragma unroll
    for (int q = 0; q < 6; q++) {
        const size_t row = tmajor ? ((size_t)0 * B_ + b0 + gq_b[q])
                                  : ((size_t)(b0 + gq_b[q]) * T_ + 0);
        greg[q] = gi[row * G_ + gq_col[q]];
    }
#pragma unroll
    for (int q = 0; q < 6; q++) gis[gq_sm[q]] = greg[q];
    __syncthreads();

    for (int t = 0; t < T_; t++) {
        const float* hprev = g_hbuf[t & 1];
        float* hnext = g_hbuf[(t & 1) ^ 1];
        const float* gcur = gis + (t & 1) * 1600;
        float* gnxt = gis + ((t + 1) & 1) * 1600;

        if (t == 0) {
            const float4 z4 = make_float4(0.f, 0.f, 0.f, 0.f);
            for (int v = tid; v < 64 * 64; v += 256) {
                const int b = v >> 6, kq = v & 63;
                *(float4*)&hs[b * 260 + kq * 4] = z4;
            }
        } else {
#pragma unroll 4
            for (int v = tid; v < 64 * 64; v += 256) {
                const int b = v >> 6, kq = v & 63;
                *(float4*)&hs[b * 260 + kq * 4] =
                    *(const float4*)&hprev[(b0 + b) * H_ + kq * 4];
            }
        }

        {
            const int tn = (t + 1 < T_) ? (t + 1) : t;
#pragma unroll
            for (int q = 0; q < 6; q++) {
                const size_t row = tmajor ? ((size_t)tn * B_ + b0 + gq_b[q])
                                          : ((size_t)(b0 + gq_b[q]) * T_ + tn);
                greg[q] = __ldg(&gi[row * G_ + gq_col[q]]);
            }
        }
        __syncthreads();

        float acc[8][6];
#pragma unroll
        for (int i = 0; i < 8; i++)
#pragma unroll
            for (int g = 0; g < 6; g++) acc[i][g] = 0.f;

#pragma unroll 4
        for (int kb = 0; kb < 8; kb++) {
            const int k = kbase + kb * 4;
            float4 wv[6];
#pragma unroll
            for (int g = 0; g < 6; g++)
                wv[g] = *(const float4*)&wsl[(g0l + g) * 260 + k];
#pragma unroll
            for (int i = 0; i < 8; i++) {
                const float4 hv = *(const float4*)&hs[(bl + 8 * i) * 260 + k];
#pragma unroll
                for (int g = 0; g < 6; g++) {
                    acc[i][g] += hv.x * wv[g].x;
                    acc[i][g] += hv.y * wv[g].y;
                    acc[i][g] += hv.z * wv[g].z;
                    acc[i][g] += hv.w * wv[g].w;
                }
            }
        }
#pragma unroll
        for (int i = 0; i < 8; i++) {
            float* p = &part[(w * 64 + bl + 8 * i) * 25 + g0l];
#pragma unroll
            for (int g = 0; g < 6; g++) p[g] = acc[i][g];
        }
#pragma unroll
        for (int q = 0; q < 6; q++) gnxt[gq_sm[q]] = greg[q];
        __syncthreads();

#pragma unroll
        for (int p = 0; p < 2; p++) {
            const int pr = tid + p * 256;
            const int b = pr & 63, jj = pr >> 6;
            float sr = bsl[jj], sz = bsl[8 + jj], sn = bsl[16 + jj];
#pragma unroll
            for (int ww = 0; ww < 8; ww++) {
                const float* pp = &part[(ww * 64 + b) * 25];
                sr += pp[jj];
                sz += pp[8 + jj];
                sn += pp[16 + jj];
            }
            sr += gcur[b * 25 + jj];
            sz += gcur[b * 25 + 8 + jj];
            const float r = __fdividef(1.f, 1.f + __expf(-sr));
            const float z = __fdividef(1.f, 1.f + __expf(-sz));
            const float a = gcur[b * 25 + 16 + jj] + r * sn;
            const float n = __fdividef(2.f, 1.f + __expf(-2.f * a)) - 1.f;
            const float hold = hs[b * 260 + j0 + jj];
            hst[b * 9 + jj] = (1.f - z) * n + z * hold;
        }
        __syncthreads();

#pragma unroll
        for (int p = 0; p < 2; p++) {
            const int idx = tid + p * 256;
            const int b = idx >> 3, jj = idx & 7;
            const float v = hst[b * 9 + jj];
            hnext[(b0 + b) * H_ + j0 + jj] = v;
            if (hseq) hseq[((size_t)t * B_ + b0 + b) * H_ + j0 + jj] = v;
        }

        __threadfence();
        __syncthreads();
        if (tid == 0) {
            const unsigned g = g_gen[grp];
            if (atomicAdd(&g_cnt[grp], 1u) == (unsigned)(GRP_CTAS - 1)) {
                g_cnt[grp] = 0;
                __threadfence();
                g_gen[grp] = g + 1u;
            } else {
                while (g_gen[grp] == g) {}
            }
            __threadfence();
        }
        __syncthreads();
    }
}

// ---------------- final FC: out[256,10] = h @ Wfc^T + bfc -------------------------
__global__ void fc_kernel(const float* __restrict__ h, const float* __restrict__ Wfc,
                          const float* __restrict__ bfc, float* __restrict__ out)
{
    const int b = blockIdx.x;
    const int lane = threadIdx.x;
    float hv[8];
#pragma unroll
    for (int i = 0; i < 8; i++) hv[i] = h[b * H_ + lane + 32 * i];
    for (int cc = 0; cc < C_; cc++) {
        float s = 0.f;
#pragma unroll
        for (int i = 0; i < 8; i++) s += hv[i] * Wfc[cc * H_ + lane + 32 * i];
#pragma unroll
        for (int o = 16; o > 0; o >>= 1) s += __shfl_down_sync(0xffffffffu, s, o);
        if (lane == 0) out[b * C_ + cc] = s + bfc[cc];
    }
}

// ---------------- launch ----------------------------------------------------------
extern "C" void kernel_launch(void* const* d_in, const int* in_sizes, int n_in,
                              void* d_out, int out_size)
{
    (void)in_sizes; (void)n_in; (void)out_size;
    const float* x    = (const float*)d_in[0];
    const float* Wih0 = (const float*)d_in[1];
    const float* Whh0 = (const float*)d_in[2];
    const float* bih0 = (const float*)d_in[3];
    const float* bhh0 = (const float*)d_in[4];
    const float* Wih1 = (const float*)d_in[5];
    const float* Whh1 = (const float*)d_in[6];
    const float* bih1 = (const float*)d_in[7];
    const float* bhh1 = (const float*)d_in[8];
    const float* Wfc  = (const float*)d_in[9];
    const float* bfc  = (const float*)d_in[10];
    float* out = (float*)d_out;

    float *p_gi, *p_h1, *p_hb;
    __nv_bfloat16 *p_ahi, *p_alo, *p_whi, *p_wlo;
    cudaGetSymbolAddress((void**)&p_gi, g_gi);
    cudaGetSymbolAddress((void**)&p_h1, g_h1);
    cudaGetSymbolAddress((void**)&p_hb, g_hbuf);
    cudaGetSymbolAddress((void**)&p_ahi, g_ahi);
    cudaGetSymbolAddress((void**)&p_alo, g_alo);
    cudaGetSymbolAddress((void**)&p_whi, g_whi);
    cudaGetSymbolAddress((void**)&p_wlo, g_wlo);

    const int scan_smem = 39488 * 4;
    cudaFuncSetAttribute(gru_scan, cudaFuncAttributeMaxDynamicSharedMemorySize, scan_smem);
    // smem = 384 padded rows * (K+8)*2 bytes; K=256 -> 202752 B
    const int gemm_smem1 = 384 * (256 + 8) * 2;
    const int gemm_smem0 = 384 * (128 + 8) * 2;
    cudaFuncSetAttribute(mma_gemm, cudaFuncAttributeMaxDynamicSharedMemorySize, gemm_smem1);

    const dim3 gtile(12, 1024);  // N-tiles fastest -> A tile reused across N in L2

    // ---- layer 0 ----
    split_bf16<<<(131072 * 128 / 4 + 255) / 256, 256>>>(x, p_ahi, p_alo, 131072 * 128 / 4);
    split_bf16<<<(G_ * D_ / 4 + 255) / 256, 256>>>(Wih0, p_whi, p_wlo, G_ * D_ / 4);
    mma_gemm<<<gtile, 256, gemm_smem0>>>(p_ahi, p_alo, p_whi, p_wlo, bih0, p_gi, D_);
    gru_scan<<<NCTA_SCAN, 256, scan_smem>>>(p_gi, Whh0, bhh0, p_h1, /*tmajor=*/0);

    // ---- layer 1 ----
    split_bf16<<<(131072 * 256 / 4 + 255) / 256, 256>>>(p_h1, p_ahi, p_alo, 131072 * 256 / 4);
    split_bf16<<<(G_ * H_ / 4 + 255) / 256, 256>>>(Wih1, p_whi, p_wlo, G_ * H_ / 4);
    mma_gemm<<<gtile, 256, gemm_smem1>>>(p_ahi, p_alo, p_whi, p_wlo, bih1, p_gi, H_);
    gru_scan<<<NCTA_SCAN, 256, scan_smem>>>(p_gi, Whh1, bhh1, nullptr, /*tmajor=*/1);

    // classifier on final hidden state (in g_hbuf[0] after 512 steps)
    fc_kernel<<<B_, 32>>>(p_hb, Wfc, bfc, out);
}

// round 9
// speedup vs baseline: 1.5394x; 1.3616x over previous
#include <cuda_runtime.h>
#include <cuda_bf16.h>
#include <math.h>
#include <stdint.h>

#define B_  256
#define T_  512
#define D_  128
#define H_  256
#define G_  768
#define C_  10

#define NCTA_SCAN 128
#define GRP_CTAS  32

// ---------------- warp-mma helpers (sm_80+ baseline; compiles for plain sm_103) ---
__device__ __forceinline__ uint32_t smem_u32(const void* p) {
    uint32_t a;
    asm("{ .reg .u64 t; cvta.to.shared.u64 t, %1; cvt.u32.u64 %0, t; }" : "=r"(a) : "l"(p));
    return a;
}
#define LDSM4(r0, r1, r2, r3, addr) \
    asm volatile("ldmatrix.sync.aligned.m8n8.x4.shared.b16 {%0,%1,%2,%3}, [%4];" \
        : "=r"(r0), "=r"(r1), "=r"(r2), "=r"(r3) : "r"(addr))
#define LDSM2(r0, r1, addr) \
    asm volatile("ldmatrix.sync.aligned.m8n8.x2.shared.b16 {%0,%1}, [%2];" \
        : "=r"(r0), "=r"(r1) : "r"(addr))
#define MMA16816(c, a, b0v, b1v) \
    asm volatile("mma.sync.aligned.m16n8k16.row.col.f32.bf16.bf16.f32 " \
        "{%0,%1,%2,%3},{%4,%5,%6,%7},{%8,%9},{%0,%1,%2,%3};" \
        : "+f"((c)[0]), "+f"((c)[1]), "+f"((c)[2]), "+f"((c)[3]) \
        : "r"((a)[0]), "r"((a)[1]), "r"((a)[2]), "r"((a)[3]), "r"(b0v), "r"(b1v))

// ---------------- scratch (device globals; no allocation allowed) ----------------
__device__ float g_gi[(size_t)B_ * T_ * G_];           // gi for current layer (~403 MB)
__device__ __nv_bfloat16 g_seqhi[(size_t)T_ * B_ * H_]; // layer-0 h sequence, bf16 hi
__device__ __nv_bfloat16 g_seqlo[(size_t)T_ * B_ * H_]; // layer-0 h sequence, bf16 lo
__device__ __nv_bfloat16 g_hbhi[2][B_ * H_];           // ping-pong h (bf16 hi)
__device__ __nv_bfloat16 g_hblo[2][B_ * H_];           // ping-pong h (bf16 lo)
__device__ float g_hlast[B_ * H_];                     // final fp32 h for the FC
__device__ volatile unsigned g_gen[4 * 32];            // per-group barrier generation
__device__ unsigned g_cnt[4 * 32];                     // per-group arrival counter
__device__ __nv_bfloat16 g_ahi[(size_t)131072 * 128];  // x split (layer-0 gi GEMM)
__device__ __nv_bfloat16 g_alo[(size_t)131072 * 128];
__device__ __nv_bfloat16 g_whi[G_ * H_];
__device__ __nv_bfloat16 g_wlo[G_ * H_];

// ---------------- fp32 -> (bf16 hi, bf16 lo) split ---------------------------------
__global__ void split_bf16(const float* __restrict__ s, __nv_bfloat16* __restrict__ hi,
                           __nv_bfloat16* __restrict__ lo, int n4)
{
    const int i = blockIdx.x * blockDim.x + threadIdx.x;
    if (i >= n4) return;
    const float4 v = ((const float4*)s)[i];
    __nv_bfloat16 h0 = __float2bfloat16(v.x);
    __nv_bfloat16 h1 = __float2bfloat16(v.y);
    __nv_bfloat16 h2 = __float2bfloat16(v.z);
    __nv_bfloat16 h3 = __float2bfloat16(v.w);
    __nv_bfloat16 l0 = __float2bfloat16(v.x - __bfloat162float(h0));
    __nv_bfloat16 l1 = __float2bfloat16(v.y - __bfloat162float(h1));
    __nv_bfloat16 l2 = __float2bfloat16(v.z - __bfloat162float(h2));
    __nv_bfloat16 l3 = __float2bfloat16(v.w - __bfloat162float(h3));
    __nv_bfloat162* hp = (__nv_bfloat162*)hi;
    __nv_bfloat162* lp = (__nv_bfloat162*)lo;
    hp[i * 2 + 0] = __nv_bfloat162(h0, h1);
    hp[i * 2 + 1] = __nv_bfloat162(h2, h3);
    lp[i * 2 + 0] = __nv_bfloat162(l0, l1);
    lp[i * 2 + 1] = __nv_bfloat162(l2, l3);
}

// ---------------- split-bf16 HMMA GEMM: C[M,768] = A[M,K]@W[768,K]^T + bias -------
// (proven in R8) CTA 128m x 64n, 8 warps (4m x 2n), warp tile 32x32.
__global__ void __launch_bounds__(256, 1) mma_gemm(
    const __nv_bfloat16* __restrict__ Ahi, const __nv_bfloat16* __restrict__ Alo,
    const __nv_bfloat16* __restrict__ Whi, const __nv_bfloat16* __restrict__ Wlo,
    const float* __restrict__ bias, float* __restrict__ C, int K)
{
    extern __shared__ char smem[];
    const int KS = K + 8;
    const int strB = KS * 2;
    char* sAhi = smem;
    char* sAlo = sAhi + 128 * strB;
    char* sWhi = sAlo + 128 * strB;
    char* sWlo = sWhi + 64 * strB;

    const int tid = threadIdx.x;
    const int n0 = blockIdx.x * 64;
    const int m0 = blockIdx.y * 128;

    const int cpr = K >> 3;
    for (int c = tid; c < 128 * cpr; c += 256) {
        const int r = c / cpr, kc = c % cpr;
        const size_t src = (size_t)(m0 + r) * K + kc * 8;
        *(uint4*)(sAhi + r * strB + kc * 16) = *(const uint4*)(Ahi + src);
        *(uint4*)(sAlo + r * strB + kc * 16) = *(const uint4*)(Alo + src);
    }
    for (int c = tid; c < 64 * cpr; c += 256) {
        const int r = c / cpr, kc = c % cpr;
        const size_t src = (size_t)(n0 + r) * K + kc * 8;
        *(uint4*)(sWhi + r * strB + kc * 16) = *(const uint4*)(Whi + src);
        *(uint4*)(sWlo + r * strB + kc * 16) = *(const uint4*)(Wlo + src);
    }
    __syncthreads();

    const int wid = tid >> 5, lane = tid & 31;
    const int mw = wid >> 1, nw = wid & 1;

    float acc[2][4][4];
#pragma unroll
    for (int mt = 0; mt < 2; mt++)
#pragma unroll
        for (int nt = 0; nt < 4; nt++)
#pragma unroll
            for (int q = 0; q < 4; q++) acc[mt][nt][q] = 0.f;

    const int aRow = mw * 32 + (lane & 15);
    const int aKof = (lane >> 4) * 16;
    const int bRow = nw * 32 + (lane & 7) + ((lane >> 4) << 3);
    const int bKof = ((lane >> 3) & 1) * 16;

    const uint32_t uAhi = smem_u32(sAhi), uAlo = smem_u32(sAlo);
    const uint32_t uWhi = smem_u32(sWhi), uWlo = smem_u32(sWlo);

    const int nks = K >> 4;
    for (int ks = 0; ks < nks; ks++) {
        const int kb = ks * 32;
        uint32_t ah[2][4], al[2][4], bh[4][2], bl[4][2];
#pragma unroll
        for (int mt = 0; mt < 2; mt++) {
            const uint32_t ra = (uint32_t)((aRow + mt * 16) * strB + kb + aKof);
            LDSM4(ah[mt][0], ah[mt][1], ah[mt][2], ah[mt][3], uAhi + ra);
            LDSM4(al[mt][0], al[mt][1], al[mt][2], al[mt][3], uAlo + ra);
        }
#pragma unroll
        for (int np = 0; np < 2; np++) {
            const uint32_t rb = (uint32_t)((bRow + np * 16) * strB + kb + bKof);
            uint32_t t0, t1, t2, t3;
            LDSM4(t0, t1, t2, t3, uWhi + rb);
            bh[np * 2][0] = t0; bh[np * 2][1] = t1;
            bh[np * 2 + 1][0] = t2; bh[np * 2 + 1][1] = t3;
            LDSM4(t0, t1, t2, t3, uWlo + rb);
            bl[np * 2][0] = t0; bl[np * 2][1] = t1;
            bl[np * 2 + 1][0] = t2; bl[np * 2 + 1][1] = t3;
        }
#pragma unroll
        for (int mt = 0; mt < 2; mt++)
#pragma unroll
            for (int nt = 0; nt < 4; nt++) {
                MMA16816(acc[mt][nt], ah[mt], bh[nt][0], bh[nt][1]);
                MMA16816(acc[mt][nt], ah[mt], bl[nt][0], bl[nt][1]);
                MMA16816(acc[mt][nt], al[mt], bh[nt][0], bh[nt][1]);
            }
    }

#pragma unroll
    for (int mt = 0; mt < 2; mt++)
#pragma unroll
        for (int nt = 0; nt < 4; nt++) {
            const int row = m0 + mw * 32 + mt * 16 + (lane >> 2);
            const int col = n0 + nw * 32 + nt * 8 + (lane & 3) * 2;
            const float b0 = bias[col], b1 = bias[col + 1];
            float2 o0, o1;
            o0.x = acc[mt][nt][0] + b0; o0.y = acc[mt][nt][1] + b1;
            o1.x = acc[mt][nt][2] + b0; o1.y = acc[mt][nt][3] + b1;
            *(float2*)&C[(size_t)row * G_ + col]       = o0;
            *(float2*)&C[(size_t)(row + 8) * G_ + col] = o1;
        }
}

// ---------------- persistent GRU scan, HMMA recurrence -----------------------------
// 128 CTAs x 256 threads. CTA (bblk 0..3, jblk 0..31): 64 batches x 8 hidden dims.
// Whh slice split hi/lo bf16 in smem; h circulates as bf16 hi/lo in global;
// per-step GEMM on mma.sync (4 m-tiles x 2 K-halves across 8 warps, 3 split passes);
// fp32 h_old resident in smem (hst) for the exact z*h term.
__global__ void __launch_bounds__(256, 1) gru_scan_mma(
    const float* __restrict__ gi, const float* __restrict__ Whh,
    const float* __restrict__ bhh,
    __nv_bfloat16* __restrict__ seqhi, __nv_bfloat16* __restrict__ seqlo, int tmajor)
{
    extern __shared__ char smc[];
    // byte offsets (all 16B aligned); padded row stride 528 B (264 bf16)
    char* swhi_c = smc;                  // [24][528]  = 12672
    char* swlo_c = smc + 12672;          // 12672
    char* shhi_c = smc + 25344;          // [64][528]  = 33792
    char* shlo_c = smc + 59136;          // 33792
    float* part  = (float*)(smc + 92928);   // [2][64][25] = 12800 B
    float* gis   = (float*)(smc + 105728);  // [2][64*25]  = 12800 B
    float* hst   = (float*)(smc + 118528);  // [64][9]     = 2304 B
    float* bsl   = (float*)(smc + 120832);  // [24]
    __nv_bfloat16* swhi = (__nv_bfloat16*)swhi_c;
    __nv_bfloat16* swlo = (__nv_bfloat16*)swlo_c;

    const int tid = threadIdx.x;
    const int cta = blockIdx.x;
    const int bblk = cta >> 5;
    const int jblk = cta & 31;
    const int b0  = bblk * 64;
    const int j0  = jblk * 8;
    const int grp = bblk * 32;

    // ---- persistent Whh slice, split hi/lo ----
    for (int idx = tid; idx < 24 * 256; idx += 256) {
        const int row = idx >> 8, k = idx & 255;
        const float v = Whh[(size_t)((row >> 3) * H_ + j0 + (row & 7)) * H_ + k];
        const __nv_bfloat16 hi = __float2bfloat16(v);
        const __nv_bfloat16 lo = __float2bfloat16(v - __bfloat162float(hi));
        swhi[row * 264 + k] = hi;
        swlo[row * 264 + k] = lo;
    }
    if (tid < 24) bsl[tid] = bhh[(tid >> 3) * H_ + j0 + (tid & 7)];
    for (int idx = tid; idx < 576; idx += 256) hst[idx] = 0.f;

    const int w = tid >> 5, lane = tid & 31;
    const int mt = w & 3, kh = w >> 2;

    // ldmatrix lane addressing (validated in R8's mma_gemm)
    const int aoff   = (mt * 16 + (lane & 15)) * 528 + (lane >> 4) * 16;
    const int boff01 = ((lane & 7) + ((lane >> 4) << 3)) * 528 + ((lane >> 3) & 1) * 16;
    const int boff2  = (16 + (lane & 7)) * 528 + ((lane >> 3) & 1) * 16;
    const uint32_t uAhi = smem_u32(shhi_c), uAlo = smem_u32(shlo_c);
    const uint32_t uWhi = smem_u32(swhi_c), uWlo = smem_u32(swlo_c);

    // per-thread gi staging map (6 elements), fixed across steps
    int gq_b[6], gq_sm[6], gq_col[6];
#pragma unroll
    for (int q = 0; q < 6; q++) {
        const int idx = tid + 256 * q;
        const int b = idx / 24, gg = idx % 24;
        gq_b[q] = b;
        gq_sm[q] = b * 25 + gg;
        gq_col[q] = (gg >> 3) * H_ + j0 + (gg & 7);
    }
    float greg[6];
#pragma unroll
    for (int q = 0; q < 6; q++) {
        const size_t row = tmajor ? ((size_t)0 * B_ + b0 + gq_b[q])
                                  : ((size_t)(b0 + gq_b[q]) * T_ + 0);
        greg[q] = gi[row * G_ + gq_col[q]];
    }
#pragma unroll
    for (int q = 0; q < 6; q++) gis[gq_sm[q]] = greg[q];
    __syncthreads();

    for (int t = 0; t < T_; t++) {
        const float* gcur = gis + (t & 1) * 1600;
        float* gnxt = gis + ((t + 1) & 1) * 1600;
        const int cur = t & 1, nxt = cur ^ 1;

        // ---- stage h_prev hi/lo (uint4, coalesced LDG / conflict-free STS) ----
        if (t == 0) {
            const uint4 z4 = make_uint4(0u, 0u, 0u, 0u);
#pragma unroll
            for (int q = 0; q < 8; q++) {
                const int v = tid + 256 * q;        // 0..2047
                const int b = v >> 5, c = v & 31;
                *(uint4*)(shhi_c + b * 528 + c * 16) = z4;
                *(uint4*)(shlo_c + b * 528 + c * 16) = z4;
            }
        } else {
#pragma unroll
            for (int q = 0; q < 8; q++) {
                const int v = tid + 256 * q;
                const int b = v >> 5, c = v & 31;
                *(uint4*)(shhi_c + b * 528 + c * 16) =
                    *(const uint4*)&g_hbhi[cur][(b0 + b) * H_ + c * 8];
                *(uint4*)(shlo_c + b * 528 + c * 16) =
                    *(const uint4*)&g_hblo[cur][(b0 + b) * H_ + c * 8];
            }
        }

        // ---- prefetch gi(t+1) into registers (hidden under GEMM) ----
        {
            const int tn = (t + 1 < T_) ? (t + 1) : t;
#pragma unroll
            for (int q = 0; q < 6; q++) {
                const size_t row = tmajor ? ((size_t)tn * B_ + b0 + gq_b[q])
                                          : ((size_t)(b0 + gq_b[q]) * T_ + tn);
                greg[q] = __ldg(&gi[row * G_ + gq_col[q]]);
            }
        }
        __syncthreads();

        // ---- HMMA partial GEMM: gh[64][24] over K-half kh, 3 split passes ----
        float a0[4] = {0.f, 0.f, 0.f, 0.f};
        float a1[4] = {0.f, 0.f, 0.f, 0.f};
        float a2[4] = {0.f, 0.f, 0.f, 0.f};
#pragma unroll
        for (int ks = 0; ks < 8; ks++) {
            const int kb = kh * 256 + ks * 32;
            uint32_t ah[4], al[4], bh01[4], bl01[4], bh2[2], bl2[2];
            LDSM4(ah[0], ah[1], ah[2], ah[3], uAhi + aoff + kb);
            LDSM4(al[0], al[1], al[2], al[3], uAlo + aoff + kb);
            LDSM4(bh01[0], bh01[1], bh01[2], bh01[3], uWhi + boff01 + kb);
            LDSM2(bh2[0], bh2[1], uWhi + boff2 + kb);
            LDSM4(bl01[0], bl01[1], bl01[2], bl01[3], uWlo + boff01 + kb);
            LDSM2(bl2[0], bl2[1], uWlo + boff2 + kb);
            MMA16816(a0, ah, bh01[0], bh01[1]);
            MMA16816(a1, ah, bh01[2], bh01[3]);
            MMA16816(a2, ah, bh2[0], bh2[1]);
            MMA16816(a0, ah, bl01[0], bl01[1]);
            MMA16816(a1, ah, bl01[2], bl01[3]);
            MMA16816(a2, ah, bl2[0], bl2[1]);
            MMA16816(a0, al, bh01[0], bh01[1]);
            MMA16816(a1, al, bh01[2], bh01[3]);
            MMA16816(a2, al, bh2[0], bh2[1]);
        }
        // store partials: fragment (row t/4 {+8}, col 2(t%4)+{0,1})
        {
            float* p = &part[(kh * 64 + mt * 16 + (lane >> 2)) * 25];
            const int col = 2 * (lane & 3);
            p[col] = a0[0];      p[col + 1] = a0[1];
            p[8 + col] = a1[0];  p[9 + col] = a1[1];
            p[16 + col] = a2[0]; p[17 + col] = a2[1];
            float* p8 = p + 8 * 25;
            p8[col] = a0[2];      p8[col + 1] = a0[3];
            p8[8 + col] = a1[2];  p8[9 + col] = a1[3];
            p8[16 + col] = a2[2]; p8[17 + col] = a2[3];
        }
#pragma unroll
        for (int q = 0; q < 6; q++) gnxt[gq_sm[q]] = greg[q];
        __syncthreads();

        // ---- reduce 2 partials + gate math (2 (b,jj) per thread) ----
        float vnew[2];
        int vb[2], vj[2];
#pragma unroll
        for (int p = 0; p < 2; p++) {
            const int pr = tid + p * 256;
            const int b = pr & 63, jj = pr >> 6;
            vb[p] = b; vj[p] = jj;
            const float* p0 = &part[b * 25];
            const float* p1 = &part[(64 + b) * 25];
            const float sr = bsl[jj] + p0[jj] + p1[jj] + gcur[b * 25 + jj];
            const float sz = bsl[8 + jj] + p0[8 + jj] + p1[8 + jj] + gcur[b * 25 + 8 + jj];
            const float sn = bsl[16 + jj] + p0[16 + jj] + p1[16 + jj];
            const float r = __fdividef(1.f, 1.f + __expf(-sr));
            const float z = __fdividef(1.f, 1.f + __expf(-sz));
            const float a = gcur[b * 25 + 16 + jj] + r * sn;
            const float n = __fdividef(2.f, 1.f + __expf(-2.f * a)) - 1.f;
            const float hold = hst[b * 9 + jj];
            vnew[p] = (1.f - z) * n + z * hold;
        }
        __syncthreads();
#pragma unroll
        for (int p = 0; p < 2; p++) hst[vb[p] * 9 + vj[p]] = vnew[p];
        __syncthreads();

        // ---- convert own slice to hi/lo and publish (threads 0..63) ----
        if (tid < 64) {
            const int b = tid;
            union { __nv_bfloat16 a[8]; uint4 u; } uhi, ulo;
            float f[8];
#pragma unroll
            for (int j = 0; j < 8; j++) {
                f[j] = hst[b * 9 + j];
                uhi.a[j] = __float2bfloat16(f[j]);
                ulo.a[j] = __float2bfloat16(f[j] - __bfloat162float(uhi.a[j]));
            }
            const size_t go = (size_t)(b0 + b) * H_ + j0;
            *(uint4*)&g_hbhi[nxt][go] = uhi.u;
            *(uint4*)&g_hblo[nxt][go] = ulo.u;
            if (seqhi) {
                const size_t so = ((size_t)t * B_ + b0 + b) * H_ + j0;
                *(uint4*)&seqhi[so] = uhi.u;
                *(uint4*)&seqlo[so] = ulo.u;
            }
            if (t == T_ - 1) {
                *(float4*)&g_hlast[go] = make_float4(f[0], f[1], f[2], f[3]);
                *(float4*)&g_hlast[go + 4] = make_float4(f[4], f[5], f[6], f[7]);
            }
        }

        // ---- per-group (32 CTA) barrier (R4-proven) ----
        __threadfence();
        __syncthreads();
        if (tid == 0) {
            const unsigned g = g_gen[grp];
            if (atomicAdd(&g_cnt[grp], 1u) == (unsigned)(GRP_CTAS - 1)) {
                g_cnt[grp] = 0;
                __threadfence();
                g_gen[grp] = g + 1u;
            } else {
                while (g_gen[grp] == g) {}
            }
            __threadfence();
        }
        __syncthreads();
    }
}

// ---------------- final FC: out[256,10] = h @ Wfc^T + bfc -------------------------
__global__ void fc_kernel(const float* __restrict__ h, const float* __restrict__ Wfc,
                          const float* __restrict__ bfc, float* __restrict__ out)
{
    const int b = blockIdx.x;
    const int lane = threadIdx.x;
    float hv[8];
#pragma unroll
    for (int i = 0; i < 8; i++) hv[i] = h[b * H_ + lane + 32 * i];
    for (int cc = 0; cc < C_; cc++) {
        float s = 0.f;
#pragma unroll
        for (int i = 0; i < 8; i++) s += hv[i] * Wfc[cc * H_ + lane + 32 * i];
#pragma unroll
        for (int o = 16; o > 0; o >>= 1) s += __shfl_down_sync(0xffffffffu, s, o);
        if (lane == 0) out[b * C_ + cc] = s + bfc[cc];
    }
}

// ---------------- launch ----------------------------------------------------------
extern "C" void kernel_launch(void* const* d_in, const int* in_sizes, int n_in,
                              void* d_out, int out_size)
{
    (void)in_sizes; (void)n_in; (void)out_size;
    const float* x    = (const float*)d_in[0];
    const float* Wih0 = (const float*)d_in[1];
    const float* Whh0 = (const float*)d_in[2];
    const float* bih0 = (const float*)d_in[3];
    const float* bhh0 = (const float*)d_in[4];
    const float* Wih1 = (const float*)d_in[5];
    const float* Whh1 = (const float*)d_in[6];
    const float* bih1 = (const float*)d_in[7];
    const float* bhh1 = (const float*)d_in[8];
    const float* Wfc  = (const float*)d_in[9];
    const float* bfc  = (const float*)d_in[10];
    float* out = (float*)d_out;

    float *p_gi, *p_hl;
    __nv_bfloat16 *p_ahi, *p_alo, *p_whi, *p_wlo, *p_shi, *p_slo;
    cudaGetSymbolAddress((void**)&p_gi, g_gi);
    cudaGetSymbolAddress((void**)&p_hl, g_hlast);
    cudaGetSymbolAddress((void**)&p_ahi, g_ahi);
    cudaGetSymbolAddress((void**)&p_alo, g_alo);
    cudaGetSymbolAddress((void**)&p_whi, g_whi);
    cudaGetSymbolAddress((void**)&p_wlo, g_wlo);
    cudaGetSymbolAddress((void**)&p_shi, g_seqhi);
    cudaGetSymbolAddress((void**)&p_slo, g_seqlo);

    const int scan_smem = 120928;
    cudaFuncSetAttribute(gru_scan_mma, cudaFuncAttributeMaxDynamicSharedMemorySize, scan_smem);
    const int gemm_smem1 = 384 * (256 + 8) * 2;
    const int gemm_smem0 = 384 * (128 + 8) * 2;
    cudaFuncSetAttribute(mma_gemm, cudaFuncAttributeMaxDynamicSharedMemorySize, gemm_smem1);

    const dim3 gtile(12, 1024);

    // ---- layer 0: gi0 = x @ Wih0^T + bih0 (rows b*T+t) ----
    split_bf16<<<(131072 * 128 / 4 + 255) / 256, 256>>>(x, p_ahi, p_alo, 131072 * 128 / 4);
    split_bf16<<<(G_ * D_ / 4 + 255) / 256, 256>>>(Wih0, p_whi, p_wlo, G_ * D_ / 4);
    mma_gemm<<<gtile, 256, gemm_smem0>>>(p_ahi, p_alo, p_whi, p_wlo, bih0, p_gi, D_);
    gru_scan_mma<<<NCTA_SCAN, 256, scan_smem>>>(p_gi, Whh0, bhh0, p_shi, p_slo, /*tmajor=*/0);

    // ---- layer 1: gi1 = h1 @ Wih1^T + bih1 (rows t*B+b, hi/lo straight from scan) ----
    split_bf16<<<(G_ * H_ / 4 + 255) / 256, 256>>>(Wih1, p_whi, p_wlo, G_ * H_ / 4);
    mma_gemm<<<gtile, 256, gemm_smem1>>>(p_shi, p_slo, p_whi, p_wlo, bih1, p_gi, H_);
    gru_scan_mma<<<NCTA_SCAN, 256, scan_smem>>>(p_gi, Whh1, bhh1, nullptr, nullptr, /*tmajor=*/1);

    // classifier on final hidden state
    fc_kernel<<<B_, 32>>>(p_hl, Wfc, bfc, out);
}